// round 13
// baseline (speedup 1.0000x reference)
#include <cuda_runtime.h>
#include <cuda_bf16.h>
#include <math.h>
#include <stdint.h>

// ---------------------------------------------------------------------------
// Problem dims (fixed by the dataset)
// ---------------------------------------------------------------------------
#define B_  2
#define T_  1024
#define D_  2048
#define NH  16
#define KH  8
#define HD  128
#define HID_ 8192
#define MT  (B_ * T_)            // 2048 token rows
#define QKVW 4096                // NH*HD + KH*HD + KH*HD
#define WINDOW 512

// ---------------------------------------------------------------------------
// Scratch (static device arrays — allocation-free per harness rules)
// ---------------------------------------------------------------------------
__device__ float g_h      [(size_t)MT * D_];
__device__ float g_wpack  [(size_t)D_ * QKVW];
__device__ float g_qkv    [(size_t)MT * QKVW];
__device__ float g_q      [(size_t)B_ * NH * T_ * HD];
__device__ float g_k      [(size_t)B_ * KH * T_ * HD];
__device__ float g_v      [(size_t)B_ * KH * T_ * HD];
__device__ float g_enc    [(size_t)MT * D_];
__device__ float g_attnraw[(size_t)MT * D_];
__device__ float g_attnout[(size_t)MT * D_];
__device__ float g_h2     [(size_t)MT * D_];
__device__ float g_gate   [(size_t)MT * HID_];
__device__ float g_up     [(size_t)MT * HID_];
__device__ float g_act    [(size_t)MT * HID_];
__device__ float g_outraw [(size_t)MT * D_];

// ---------------------------------------------------------------------------
// Block reduction (256 threads)
// ---------------------------------------------------------------------------
__device__ __forceinline__ float blockSum256(float v) {
    __shared__ float sm[8];
    v += __shfl_xor_sync(0xffffffffu, v, 16);
    v += __shfl_xor_sync(0xffffffffu, v, 8);
    v += __shfl_xor_sync(0xffffffffu, v, 4);
    v += __shfl_xor_sync(0xffffffffu, v, 2);
    v += __shfl_xor_sync(0xffffffffu, v, 1);
    if ((threadIdx.x & 31) == 0) sm[threadIdx.x >> 5] = v;
    __syncthreads();
    float t = sm[0] + sm[1] + sm[2] + sm[3] + sm[4] + sm[5] + sm[6] + sm[7];
    __syncthreads();
    return t;
}

// ---------------------------------------------------------------------------
// Pre-attn RMSNorm
// ---------------------------------------------------------------------------
__global__ __launch_bounds__(256) void rmsnorm_kernel(
    const float* __restrict__ in, const float* __restrict__ scale,
    float* __restrict__ out)
{
    const size_t base = (size_t)blockIdx.x * D_;
    float loc[8]; float ss = 0.f;
#pragma unroll
    for (int j = 0; j < 8; j++) {
        float v = in[base + threadIdx.x + j * 256];
        loc[j] = v; ss += v * v;
    }
    float tot = blockSum256(ss);
    float r = rsqrtf(tot * (1.f / D_) + 1e-6f);
#pragma unroll
    for (int j = 0; j < 8; j++) {
        int idx = threadIdx.x + j * 256;
        out[base + idx] = loc[j] * r * (1.f + scale[idx]);
    }
}

// ---------------------------------------------------------------------------
// Pack q_kernel [N,D,H] and kv_kernel [2,K,D,H] into Wpack [D, 4096]
// ---------------------------------------------------------------------------
__global__ __launch_bounds__(256) void pack_kernel(
    const float* __restrict__ qk, const float* __restrict__ kvk)
{
    size_t i = (size_t)blockIdx.x * blockDim.x + threadIdx.x;
    const size_t total = (size_t)D_ * QKVW;
    if (i >= total) return;
    int d = (int)(i >> 12);
    int col = (int)(i & (QKVW - 1));
    float v;
    if (col < 2048) {
        int n = col >> 7, hh = col & 127;
        v = qk[((size_t)n * D_ + d) * HD + hh];
    } else if (col < 3072) {
        int cc = col - 2048; int kk2 = cc >> 7, hh = cc & 127;
        v = kvk[((size_t)kk2 * D_ + d) * HD + hh];
    } else {
        int cc = col - 3072; int kk2 = cc >> 7, hh = cc & 127;
        v = kvk[(size_t)KH * D_ * HD + ((size_t)kk2 * D_ + d) * HD + hh];
    }
    g_wpack[i] = v;
}

// ---------------------------------------------------------------------------
// TF32 tensor-core GEMM: C[M,N] = A[M,K] * B[K,N], row-major.
// M%128==0, N%128==0, K%16==0.
// 256 threads = 8 warps in 2x4; each warp computes 64x32 via 4x4 m16n8k8 tiles.
// Inputs rounded to tf32 (cvt.rna) during smem staging; fp32 accumulate.
// True prefetch: LDG next tile into regs -> MMA current tile -> STS next.
// Smem double-buffered, +8-word row pad -> conflict-free fragment LDS.
// ---------------------------------------------------------------------------
#define GBM 128
#define GBN 128
#define GBK 16
#define GPAD 8

__device__ __forceinline__ uint32_t f2tf32(float x) {
    uint32_t u;
    asm("cvt.rna.tf32.f32 %0, %1;" : "=r"(u) : "f"(x));
    return u;
}

__device__ __forceinline__ void mma_tf32(
    float c[4], const uint32_t a[4], const uint32_t b[2])
{
    asm volatile(
        "mma.sync.aligned.m16n8k8.row.col.f32.tf32.tf32.f32 "
        "{%0,%1,%2,%3}, {%4,%5,%6,%7}, {%8,%9}, {%0,%1,%2,%3};"
        : "+f"(c[0]), "+f"(c[1]), "+f"(c[2]), "+f"(c[3])
        : "r"(a[0]), "r"(a[1]), "r"(a[2]), "r"(a[3]),
          "r"(b[0]), "r"(b[1]));
}

__global__ __launch_bounds__(256) void gemm_tf32(
    const float* __restrict__ A, const float* __restrict__ B,
    float* __restrict__ C, int M, int N, int K)
{
    __shared__ uint32_t As[2][GBK][GBM + GPAD];   // k-major (transposed)
    __shared__ uint32_t Bs[2][GBK][GBN + GPAD];

    const int tid = threadIdx.x;
    const int lane = tid & 31;
    const int wid = tid >> 5;
    const int warpRow = wid >> 2;           // 0..1 -> 64-row slab
    const int warpCol = wid & 3;            // 0..3 -> 32-col slab
    const int gid = lane >> 2;              // groupID 0..7
    const int tig = lane & 3;               // thread-in-group 0..3

    const float* Ablk = A + (size_t)blockIdx.y * GBM * K;
    const float* Bblk = B + (size_t)blockIdx.x * GBN;

    // staging thread mapping
    const int arow = tid >> 1;              // 0..127
    const int acg  = (tid & 1) << 3;        // k-subgroup 0 or 8
    const int brow = tid >> 4;              // 0..15
    const int bcol = (tid & 15) << 3;       // 0..120

    float acc[4][4][4];
#pragma unroll
    for (int mt = 0; mt < 4; mt++)
#pragma unroll
        for (int nt = 0; nt < 4; nt++)
#pragma unroll
            for (int r = 0; r < 4; r++) acc[mt][nt][r] = 0.f;

    float4 ra0, ra1, rb0, rb1;              // prefetch registers

#define LDG_TILE(k0)                                                           \
    {                                                                          \
        ra0 = *(const float4*)(Ablk + (size_t)arow * K + (k0) + acg);          \
        ra1 = *(const float4*)(Ablk + (size_t)arow * K + (k0) + acg + 4);      \
        rb0 = *(const float4*)(Bblk + (size_t)((k0) + brow) * N + bcol);       \
        rb1 = *(const float4*)(Bblk + (size_t)((k0) + brow) * N + bcol + 4);   \
    }

#define STS_TILE(buf)                                                          \
    {                                                                          \
        As[buf][acg + 0][arow] = f2tf32(ra0.x);                                \
        As[buf][acg + 1][arow] = f2tf32(ra0.y);                                \
        As[buf][acg + 2][arow] = f2tf32(ra0.z);                                \
        As[buf][acg + 3][arow] = f2tf32(ra0.w);                                \
        As[buf][acg + 4][arow] = f2tf32(ra1.x);                                \
        As[buf][acg + 5][arow] = f2tf32(ra1.y);                                \
        As[buf][acg + 6][arow] = f2tf32(ra1.z);                                \
        As[buf][acg + 7][arow] = f2tf32(ra1.w);                                \
        uint4 ub0 = make_uint4(f2tf32(rb0.x), f2tf32(rb0.y),                   \
                               f2tf32(rb0.z), f2tf32(rb0.w));                  \
        uint4 ub1 = make_uint4(f2tf32(rb1.x), f2tf32(rb1.y),                   \
                               f2tf32(rb1.z), f2tf32(rb1.w));                  \
        *(uint4*)(&Bs[buf][brow][bcol])     = ub0;                             \
        *(uint4*)(&Bs[buf][brow][bcol + 4]) = ub1;                             \
    }

    LDG_TILE(0);
    STS_TILE(0);
    __syncthreads();

    int cur = 0;
    for (int k0 = 0; k0 < K; k0 += GBK) {
        const bool has_next = (k0 + GBK) < K;
        if (has_next) LDG_TILE(k0 + GBK);   // in-flight during MMA below

#pragma unroll
        for (int ks = 0; ks < 2; ks++) {
            const int k8 = ks * 8;
            uint32_t afr[4][4], bfr[4][2];
#pragma unroll
            for (int mt = 0; mt < 4; mt++) {
                int m0 = warpRow * 64 + mt * 16 + gid;
                afr[mt][0] = As[cur][k8 + tig][m0];
                afr[mt][1] = As[cur][k8 + tig][m0 + 8];
                afr[mt][2] = As[cur][k8 + tig + 4][m0];
                afr[mt][3] = As[cur][k8 + tig + 4][m0 + 8];
            }
#pragma unroll
            for (int nt = 0; nt < 4; nt++) {
                int n0 = warpCol * 32 + nt * 8 + gid;
                bfr[nt][0] = Bs[cur][k8 + tig][n0];
                bfr[nt][1] = Bs[cur][k8 + tig + 4][n0];
            }
#pragma unroll
            for (int mt = 0; mt < 4; mt++)
#pragma unroll
                for (int nt = 0; nt < 4; nt++)
                    mma_tf32(acc[mt][nt], afr[mt], bfr[nt]);
        }
        if (has_next) STS_TILE(cur ^ 1);    // other buffer: no race w/ readers
        __syncthreads();
        cur ^= 1;
    }
#undef LDG_TILE
#undef STS_TILE

    // Epilogue: c0 (gid, 2*tig), c1 (gid, 2*tig+1), c2 (+8 row), c3.
    const size_t crowbase = (size_t)blockIdx.y * GBM + warpRow * 64;
    const int ccolbase = blockIdx.x * GBN + warpCol * 32;
#pragma unroll
    for (int mt = 0; mt < 4; mt++) {
#pragma unroll
        for (int nt = 0; nt < 4; nt++) {
            size_t r0 = crowbase + mt * 16 + gid;
            int c0 = ccolbase + nt * 8 + tig * 2;
            *(float2*)(C + r0 * N + c0) =
                make_float2(acc[mt][nt][0], acc[mt][nt][1]);
            *(float2*)(C + (r0 + 8) * N + c0) =
                make_float2(acc[mt][nt][2], acc[mt][nt][3]);
        }
    }
}

// ---------------------------------------------------------------------------
// QK RMSNorm + RoPE + query scaling; also scatters V into [B,K,T,H] layout.
// ---------------------------------------------------------------------------
__global__ __launch_bounds__(128) void qk_rope_kernel(
    const int* __restrict__ segpos,
    const float* __restrict__ qns, const float* __restrict__ kns)
{
    const int row = blockIdx.x;       // b*T + t
    const int u = blockIdx.y;         // 0..31
    const int h = threadIdx.x;        // 0..127
    const int b = row >> 10;
    const int t = row & (T_ - 1);

    if (u >= NH + KH) {               // V: plain copy into [B,K,T,H]
        int kk = u - NH - KH;
        g_v[(((size_t)b * KH + kk) * T_ + t) * HD + h] =
            g_qkv[(size_t)row * QKVW + 3072 + kk * HD + h];
        return;
    }
    const bool isq = (u < NH);
    const int head = isq ? u : (u - NH);
    float val = g_qkv[(size_t)row * QKVW + (isq ? head * HD : 2048 + head * HD) + h];

    float ss = val * val;
    ss += __shfl_xor_sync(0xffffffffu, ss, 16);
    ss += __shfl_xor_sync(0xffffffffu, ss, 8);
    ss += __shfl_xor_sync(0xffffffffu, ss, 4);
    ss += __shfl_xor_sync(0xffffffffu, ss, 2);
    ss += __shfl_xor_sync(0xffffffffu, ss, 1);
    __shared__ float wsum[4];
    if ((h & 31) == 0) wsum[h >> 5] = ss;
    __syncthreads();
    float tot = wsum[0] + wsum[1] + wsum[2] + wsum[3];
    float r = rsqrtf(tot * (1.f / HD) + 1e-6f);
    float sc = isq ? qns[h] : kns[h];
    __shared__ float sv[HD];
    sv[h] = val * r * (1.f + sc);
    __syncthreads();

    int i = h & 63;
    float ts = powf(10000.0f, (float)i * (1.0f / 64.0f));
    float ang = (float)segpos[row] / ts;
    float s, c;
    sincosf(ang, &s, &c);
    float out;
    if (h < 64) out = sv[h] * c - sv[h + 64] * s;
    else        out = sv[h] * c + sv[h - 64] * s;

    if (isq) {
        out *= 0.08838834764831845f;  // 128^-0.5
        g_q[(((size_t)b * NH + head) * T_ + t) * HD + h] = out;
    } else {
        g_k[(((size_t)b * KH + head) * T_ + t) * HD + h] = out;
    }
}

// ---------------------------------------------------------------------------
// Sliding-window GQA attention with tanh soft-cap (fp32, no online max).
// grid: (T/32, NH, B); block 128. Each 8-lane group handles 2 queries.
// ---------------------------------------------------------------------------
__global__ __launch_bounds__(128) void attn_kernel()
{
    const int b = blockIdx.z, n = blockIdx.y;
    const int q0 = blockIdx.x * 32;
    const int kh = n >> 1;                       // G = NH/KH = 2
    const int w = threadIdx.x >> 5, lane = threadIdx.x & 31;
    const int g = lane >> 3, sub = lane & 7;
    const int qA = q0 + (w * 4 + g) * 2;
    const int qB = qA + 1;

    const float* Kbase = g_k + (size_t)(b * KH + kh) * T_ * HD;
    const float* Vbase = g_v + (size_t)(b * KH + kh) * T_ * HD;
    const float* QbA   = g_q + (((size_t)(b * NH + n)) * T_ + qA) * HD;

    __shared__ float Ks[32 * HD];
    __shared__ float Vs[32 * HD];

    int doff[16];
#pragma unroll
    for (int j = 0; j < 16; j++) doff[j] = sub * 16 + ((j + sub) & 15);

    float qrA[16], qrB[16], oA[16], oB[16];
#pragma unroll
    for (int j = 0; j < 16; j++) {
        qrA[j] = QbA[doff[j]];
        qrB[j] = QbA[HD + doff[j]];
        oA[j] = 0.f; oB[j] = 0.f;
    }
    float dA = 0.f, dB = 0.f;

    int cstart = q0 - (WINDOW - 1);
    if (cstart < 0) cstart = 0;
    cstart &= ~31;

    for (int c = cstart; c <= q0 + 31; c += 32) {
        __syncthreads();
#pragma unroll
        for (int it = 0; it < 8; it++) {
            int idx = threadIdx.x + it * 128;     // float4 index 0..1023
            int r = idx >> 5, c4 = (idx & 31) << 2;
            *(float4*)(Ks + r * HD + c4) =
                *(const float4*)(Kbase + (size_t)(c + r) * HD + c4);
            *(float4*)(Vs + r * HD + c4) =
                *(const float4*)(Vbase + (size_t)(c + r) * HD + c4);
        }
        __syncthreads();
        for (int kk = 0; kk < 32; kk++) {
            const int tk = c + kk;
            float pa = 0.f, pb = 0.f;
            const float* kr = Ks + kk * HD;
#pragma unroll
            for (int j = 0; j < 16; j++) {
                float kv = kr[doff[j]];
                pa += qrA[j] * kv;
                pb += qrB[j] * kv;
            }
            pa += __shfl_xor_sync(0xffffffffu, pa, 1);
            pa += __shfl_xor_sync(0xffffffffu, pa, 2);
            pa += __shfl_xor_sync(0xffffffffu, pa, 4);
            pb += __shfl_xor_sync(0xffffffffu, pb, 1);
            pb += __shfl_xor_sync(0xffffffffu, pb, 2);
            pb += __shfl_xor_sync(0xffffffffu, pb, 4);
            float ca = 50.f * tanhf(pa * 0.02f);
            float cb = 50.f * tanhf(pb * 0.02f);
            float ea = (tk <= qA && tk > qA - WINDOW) ? __expf(ca) : 0.f;
            float eb = (tk <= qB && tk > qB - WINDOW) ? __expf(cb) : 0.f;
            dA += ea; dB += eb;
            const float* vr = Vs + kk * HD;
#pragma unroll
            for (int j = 0; j < 16; j++) {
                float vv = vr[doff[j]];
                oA[j] += ea * vv;
                oB[j] += eb * vv;
            }
        }
    }
    float iA = 1.f / dA, iB = 1.f / dB;
    float* encA = g_enc + ((size_t)(b * T_ + qA)) * D_ + n * HD;
#pragma unroll
    for (int j = 0; j < 16; j++) {
        encA[doff[j]]      = oA[j] * iA;
        encA[D_ + doff[j]] = oB[j] * iB;
    }
}

// ---------------------------------------------------------------------------
// Fused: attn_out = rmsnorm(attn_raw)*(1+post_s) + x ; h2 = rmsnorm(attn_out)*(1+pre_ffw)
// ---------------------------------------------------------------------------
__global__ __launch_bounds__(256) void postattn_kernel(
    const float* __restrict__ x,
    const float* __restrict__ ps, const float* __restrict__ fs)
{
    const size_t base = (size_t)blockIdx.x * D_;
    float loc[8]; float ss = 0.f;
#pragma unroll
    for (int j = 0; j < 8; j++) {
        float v = g_attnraw[base + threadIdx.x + j * 256];
        loc[j] = v; ss += v * v;
    }
    float tot = blockSum256(ss);
    float r1 = rsqrtf(tot * (1.f / D_) + 1e-6f);
    float ao[8]; float ss2 = 0.f;
#pragma unroll
    for (int j = 0; j < 8; j++) {
        int idx = threadIdx.x + j * 256;
        float v = loc[j] * r1 * (1.f + ps[idx]) + x[base + idx];
        ao[j] = v; ss2 += v * v;
        g_attnout[base + idx] = v;
    }
    float tot2 = blockSum256(ss2);
    float r2 = rsqrtf(tot2 * (1.f / D_) + 1e-6f);
#pragma unroll
    for (int j = 0; j < 8; j++) {
        int idx = threadIdx.x + j * 256;
        g_h2[base + idx] = ao[j] * r2 * (1.f + fs[idx]);
    }
}

// ---------------------------------------------------------------------------
// act = gelu_tanh(gate) * up
// ---------------------------------------------------------------------------
__global__ __launch_bounds__(256) void gelu_mul_kernel()
{
    size_t i4 = (size_t)blockIdx.x * blockDim.x + threadIdx.x;
    const size_t total4 = (size_t)MT * HID_ / 4;
    if (i4 >= total4) return;
    float4 gv = ((const float4*)g_gate)[i4];
    float4 uv = ((const float4*)g_up)[i4];
    float r[4]; float gs[4] = {gv.x, gv.y, gv.z, gv.w};
    float us[4] = {uv.x, uv.y, uv.z, uv.w};
#pragma unroll
    for (int j = 0; j < 4; j++) {
        float x = gs[j];
        float t = tanhf(0.7978845608028654f * (x + 0.044715f * x * x * x));
        r[j] = 0.5f * x * (1.f + t) * us[j];
    }
    ((float4*)g_act)[i4] = make_float4(r[0], r[1], r[2], r[3]);
}

// ---------------------------------------------------------------------------
// Final: out = rmsnorm(out_raw)*(1+post_ffw) + attn_out
// ---------------------------------------------------------------------------
__global__ __launch_bounds__(256) void final_kernel(
    const float* __restrict__ ps, float* __restrict__ out)
{
    const size_t base = (size_t)blockIdx.x * D_;
    float loc[8]; float ss = 0.f;
#pragma unroll
    for (int j = 0; j < 8; j++) {
        float v = g_outraw[base + threadIdx.x + j * 256];
        loc[j] = v; ss += v * v;
    }
    float tot = blockSum256(ss);
    float r = rsqrtf(tot * (1.f / D_) + 1e-6f);
#pragma unroll
    for (int j = 0; j < 8; j++) {
        int idx = threadIdx.x + j * 256;
        out[base + idx] = loc[j] * r * (1.f + ps[idx]) + g_attnout[base + idx];
    }
}

// ---------------------------------------------------------------------------
// Launch
// ---------------------------------------------------------------------------
extern "C" void kernel_launch(void* const* d_in, const int* in_sizes, int n_in,
                              void* d_out, int out_size)
{
    const float* x        = (const float*)d_in[0];
    const int*   segpos   = (const int*)d_in[1];
    /* d_in[2] = attn_mask (causal tril) — mask computed analytically */
    const float* qkern    = (const float*)d_in[3];
    const float* kvkern   = (const float*)d_in[4];
    const float* okern    = (const float*)d_in[5];
    const float* gate_w   = (const float*)d_in[6];
    const float* up_w     = (const float*)d_in[7];
    const float* down_w   = (const float*)d_in[8];
    const float* pre_attn = (const float*)d_in[9];
    const float* post_attn= (const float*)d_in[10];
    const float* pre_ffw  = (const float*)d_in[11];
    const float* post_ffw = (const float*)d_in[12];
    const float* qns      = (const float*)d_in[13];
    const float* kns      = (const float*)d_in[14];
    float* out = (float*)d_out;

    float *p_h, *p_wpack, *p_qkv, *p_enc, *p_araw, *p_h2, *p_gate, *p_up,
          *p_act, *p_oraw;
    cudaGetSymbolAddress((void**)&p_h, g_h);
    cudaGetSymbolAddress((void**)&p_wpack, g_wpack);
    cudaGetSymbolAddress((void**)&p_qkv, g_qkv);
    cudaGetSymbolAddress((void**)&p_enc, g_enc);
    cudaGetSymbolAddress((void**)&p_araw, g_attnraw);
    cudaGetSymbolAddress((void**)&p_h2, g_h2);
    cudaGetSymbolAddress((void**)&p_gate, g_gate);
    cudaGetSymbolAddress((void**)&p_up, g_up);
    cudaGetSymbolAddress((void**)&p_act, g_act);
    cudaGetSymbolAddress((void**)&p_oraw, g_outraw);

    // 1. pre-attn rmsnorm
    rmsnorm_kernel<<<MT, 256>>>(x, pre_attn, p_h);

    // 2. pack qkv weights into [D, 4096]
    {
        size_t total = (size_t)D_ * QKVW;
        pack_kernel<<<(unsigned)((total + 255) / 256), 256>>>(qkern, kvkern);
    }

    // 3. QKV GEMM: [2048,2048] x [2048,4096]
    gemm_tf32<<<dim3(QKVW / GBN, MT / GBM), 256>>>(p_h, p_wpack, p_qkv, MT, QKVW, D_);

    // 4. QK norm + RoPE + scatter
    qk_rope_kernel<<<dim3(MT, NH + 2 * KH), 128>>>(segpos, qns, kns);

    // 5. attention
    attn_kernel<<<dim3(T_ / 32, NH, B_), 128>>>();

    // 6. O projection: [2048,2048] x [2048,2048]
    gemm_tf32<<<dim3(D_ / GBN, MT / GBM), 256>>>(p_enc, okern, p_araw, MT, D_, D_);

    // 7. post-attn norm + residual + pre-ffw norm
    postattn_kernel<<<MT, 256>>>(x, post_attn, pre_ffw);

    // 8. MLP up/gate GEMMs: [2048,2048] x [2048,8192]
    gemm_tf32<<<dim3(HID_ / GBN, MT / GBM), 256>>>(p_h2, gate_w, p_gate, MT, HID_, D_);
    gemm_tf32<<<dim3(HID_ / GBN, MT / GBM), 256>>>(p_h2, up_w, p_up, MT, HID_, D_);

    // 9. gated GELU
    {
        size_t total4 = (size_t)MT * HID_ / 4;
        gelu_mul_kernel<<<(unsigned)((total4 + 255) / 256), 256>>>();
    }

    // 10. down GEMM: [2048,8192] x [8192,2048]
    gemm_tf32<<<dim3(D_ / GBN, MT / GBM), 256>>>(p_act, down_w, p_oraw, MT, D_, HID_);

    // 11. final norm + residual
    final_kernel<<<MT, 256>>>(post_ffw, out);
}

// round 14
// speedup vs baseline: 1.0075x; 1.0075x over previous
#include <cuda_runtime.h>
#include <cuda_bf16.h>
#include <math.h>
#include <stdint.h>

// ---------------------------------------------------------------------------
// Problem dims (fixed by the dataset)
// ---------------------------------------------------------------------------
#define B_  2
#define T_  1024
#define D_  2048
#define NH  16
#define KH  8
#define HD  128
#define HID_ 8192
#define MT  (B_ * T_)            // 2048 token rows
#define QKVW 4096                // NH*HD + KH*HD + KH*HD
#define WINDOW 512

// ---------------------------------------------------------------------------
// Scratch (static device arrays — allocation-free per harness rules)
// ---------------------------------------------------------------------------
__device__ float g_h      [(size_t)MT * D_];
__device__ float g_wpack  [(size_t)D_ * QKVW];
__device__ float g_qkv    [(size_t)MT * QKVW];
__device__ float g_q      [(size_t)B_ * NH * T_ * HD];
__device__ float g_k      [(size_t)B_ * KH * T_ * HD];
__device__ float g_v      [(size_t)B_ * KH * T_ * HD];
__device__ float g_enc    [(size_t)MT * D_];
__device__ float g_attnraw[(size_t)MT * D_];
__device__ float g_attnout[(size_t)MT * D_];
__device__ float g_h2     [(size_t)MT * D_];
__device__ float g_gate   [(size_t)MT * HID_];
__device__ float g_up     [(size_t)MT * HID_];
__device__ float g_act    [(size_t)MT * HID_];
__device__ float g_outraw [(size_t)MT * D_];

// ---------------------------------------------------------------------------
// Block reduction (256 threads)
// ---------------------------------------------------------------------------
__device__ __forceinline__ float blockSum256(float v) {
    __shared__ float sm[8];
    v += __shfl_xor_sync(0xffffffffu, v, 16);
    v += __shfl_xor_sync(0xffffffffu, v, 8);
    v += __shfl_xor_sync(0xffffffffu, v, 4);
    v += __shfl_xor_sync(0xffffffffu, v, 2);
    v += __shfl_xor_sync(0xffffffffu, v, 1);
    if ((threadIdx.x & 31) == 0) sm[threadIdx.x >> 5] = v;
    __syncthreads();
    float t = sm[0] + sm[1] + sm[2] + sm[3] + sm[4] + sm[5] + sm[6] + sm[7];
    __syncthreads();
    return t;
}

// ---------------------------------------------------------------------------
// Pre-attn RMSNorm
// ---------------------------------------------------------------------------
__global__ __launch_bounds__(256) void rmsnorm_kernel(
    const float* __restrict__ in, const float* __restrict__ scale,
    float* __restrict__ out)
{
    const size_t base = (size_t)blockIdx.x * D_;
    float loc[8]; float ss = 0.f;
#pragma unroll
    for (int j = 0; j < 8; j++) {
        float v = in[base + threadIdx.x + j * 256];
        loc[j] = v; ss += v * v;
    }
    float tot = blockSum256(ss);
    float r = rsqrtf(tot * (1.f / D_) + 1e-6f);
#pragma unroll
    for (int j = 0; j < 8; j++) {
        int idx = threadIdx.x + j * 256;
        out[base + idx] = loc[j] * r * (1.f + scale[idx]);
    }
}

// ---------------------------------------------------------------------------
// Pack q_kernel [N,D,H] and kv_kernel [2,K,D,H] into Wpack [D, 4096]
// ---------------------------------------------------------------------------
__global__ __launch_bounds__(256) void pack_kernel(
    const float* __restrict__ qk, const float* __restrict__ kvk)
{
    size_t i = (size_t)blockIdx.x * blockDim.x + threadIdx.x;
    const size_t total = (size_t)D_ * QKVW;
    if (i >= total) return;
    int d = (int)(i >> 12);
    int col = (int)(i & (QKVW - 1));
    float v;
    if (col < 2048) {
        int n = col >> 7, hh = col & 127;
        v = qk[((size_t)n * D_ + d) * HD + hh];
    } else if (col < 3072) {
        int cc = col - 2048; int kk2 = cc >> 7, hh = cc & 127;
        v = kvk[((size_t)kk2 * D_ + d) * HD + hh];
    } else {
        int cc = col - 3072; int kk2 = cc >> 7, hh = cc & 127;
        v = kvk[(size_t)KH * D_ * HD + ((size_t)kk2 * D_ + d) * HD + hh];
    }
    g_wpack[i] = v;
}

// ---------------------------------------------------------------------------
// TF32 tensor-core GEMM with 3-stage cp.async pipeline.
// C[M,N] = A[M,K] * B[K,N], row-major. M%128==0, N%128==0, K%16==0 (K/16>=3).
// 256 threads = 8 warps in 2x4; each warp computes 64x32 via 4x4 m16n8k8 tiles.
// A staged m-major (row pad 20 words), B k-row-major (row pad->136 words);
// both bank-conflict-free for fragment LDS (audited: A 20g+t, B 8t+g patterns).
// fp32 in smem; cvt.rna to tf32 applied on fragments (numerically identical
// to pre-conversion). fp32 accumulate.
// ---------------------------------------------------------------------------
#define GBM 128
#define GBN 128
#define GBK 16
#define A_STRIDE 20                        // words per A row (16 data + 4 pad)
#define B_STRIDE 136                       // words per B row (128 data + 8 pad)
#define A_BYTES (GBM * A_STRIDE * 4)       // 10240
#define B_BYTES (GBK * B_STRIDE * 4)       // 8704
#define STAGE_BYTES (A_BYTES + B_BYTES)    // 18944
#define GEMM_SMEM (3 * STAGE_BYTES)        // 56832

__device__ __forceinline__ uint32_t f2tf32(float x) {
    uint32_t u;
    asm("cvt.rna.tf32.f32 %0, %1;" : "=r"(u) : "f"(x));
    return u;
}

__device__ __forceinline__ void cp16(void* sdst, const void* gsrc) {
    unsigned s = (unsigned)__cvta_generic_to_shared(sdst);
    asm volatile("cp.async.cg.shared.global [%0], [%1], 16;"
                 :: "r"(s), "l"(gsrc) : "memory");
}

__device__ __forceinline__ void mma_tf32(
    float c[4], const uint32_t a[4], const uint32_t b[2])
{
    asm volatile(
        "mma.sync.aligned.m16n8k8.row.col.f32.tf32.tf32.f32 "
        "{%0,%1,%2,%3}, {%4,%5,%6,%7}, {%8,%9}, {%0,%1,%2,%3};"
        : "+f"(c[0]), "+f"(c[1]), "+f"(c[2]), "+f"(c[3])
        : "r"(a[0]), "r"(a[1]), "r"(a[2]), "r"(a[3]),
          "r"(b[0]), "r"(b[1]));
}

__global__ __launch_bounds__(256) void gemm_tf32(
    const float* __restrict__ A, const float* __restrict__ B,
    float* __restrict__ C, int M, int N, int K)
{
    extern __shared__ char smem[];

    const int tid = threadIdx.x;
    const int lane = tid & 31;
    const int wid = tid >> 5;
    const int warpRow = wid >> 2;           // 0..1 -> 64-row slab
    const int warpCol = wid & 3;            // 0..3 -> 32-col slab
    const int gid = lane >> 2;              // groupID 0..7
    const int tig = lane & 3;               // thread-in-group 0..3

    const float* Ablk = A + (size_t)blockIdx.y * GBM * K;
    const float* Bblk = B + (size_t)blockIdx.x * GBN;

    // staging thread mapping: per thread 2x16B for A, 2x16B for B
    const int arow = tid >> 1;              // 0..127
    const int acg  = (tid & 1) << 3;        // k-subgroup 0 or 8
    const int brow = tid >> 4;              // 0..15
    const int bcol = (tid & 15) << 3;       // 0..120

    float acc[4][4][4];
#pragma unroll
    for (int mt = 0; mt < 4; mt++)
#pragma unroll
        for (int nt = 0; nt < 4; nt++)
#pragma unroll
            for (int r = 0; r < 4; r++) acc[mt][nt][r] = 0.f;

#define A_ST(s) ((float*)(smem + (s) * STAGE_BYTES))
#define B_ST(s) ((float*)(smem + (s) * STAGE_BYTES + A_BYTES))

#define ISSUE_TILE(s, k0)                                                      \
    {                                                                          \
        float* As_ = A_ST(s) + arow * A_STRIDE + acg;                          \
        const float* ag = Ablk + (size_t)arow * K + (k0) + acg;                \
        cp16(As_, ag);                                                         \
        cp16(As_ + 4, ag + 4);                                                 \
        float* Bs_ = B_ST(s) + brow * B_STRIDE + bcol;                         \
        const float* bg = Bblk + (size_t)((k0) + brow) * N + bcol;             \
        cp16(Bs_, bg);                                                         \
        cp16(Bs_ + 4, bg + 4);                                                 \
        asm volatile("cp.async.commit_group;" ::: "memory");                   \
    }

    const int T = K / GBK;                  // >= 128 for all our shapes
    ISSUE_TILE(0, 0);
    ISSUE_TILE(1, GBK);

    int cur = 0;
    for (int k = 0; k < T; k++) {
        if (k + 1 < T) {
            asm volatile("cp.async.wait_group 1;" ::: "memory");
        } else {
            asm volatile("cp.async.wait_group 0;" ::: "memory");
        }
        __syncthreads();
        if (k + 2 < T) {
            int s = (k + 2) % 3;            // == (k-1)%3: consumers passed barrier
            ISSUE_TILE(s, (k + 2) * GBK);
        }

        const float* As = A_ST(cur);
        const float* Bs = B_ST(cur);
#pragma unroll
        for (int ks = 0; ks < 2; ks++) {
            const int k8 = ks * 8;
            uint32_t afr[4][4], bfr[4][2];
#pragma unroll
            for (int mt = 0; mt < 4; mt++) {
                int m0 = warpRow * 64 + mt * 16 + gid;
                afr[mt][0] = f2tf32(As[(size_t)m0 * A_STRIDE + k8 + tig]);
                afr[mt][1] = f2tf32(As[(size_t)(m0 + 8) * A_STRIDE + k8 + tig]);
                afr[mt][2] = f2tf32(As[(size_t)m0 * A_STRIDE + k8 + tig + 4]);
                afr[mt][3] = f2tf32(As[(size_t)(m0 + 8) * A_STRIDE + k8 + tig + 4]);
            }
#pragma unroll
            for (int nt = 0; nt < 4; nt++) {
                int n0 = warpCol * 32 + nt * 8 + gid;
                bfr[nt][0] = f2tf32(Bs[(size_t)(k8 + tig) * B_STRIDE + n0]);
                bfr[nt][1] = f2tf32(Bs[(size_t)(k8 + tig + 4) * B_STRIDE + n0]);
            }
#pragma unroll
            for (int mt = 0; mt < 4; mt++)
#pragma unroll
                for (int nt = 0; nt < 4; nt++)
                    mma_tf32(acc[mt][nt], afr[mt], bfr[nt]);
        }
        cur = (cur + 1) % 3;
    }
#undef ISSUE_TILE
#undef A_ST
#undef B_ST

    // Epilogue: c0 (gid, 2*tig), c1 (gid, 2*tig+1), c2 (+8 row), c3.
    const size_t crowbase = (size_t)blockIdx.y * GBM + warpRow * 64;
    const int ccolbase = blockIdx.x * GBN + warpCol * 32;
#pragma unroll
    for (int mt = 0; mt < 4; mt++) {
#pragma unroll
        for (int nt = 0; nt < 4; nt++) {
            size_t r0 = crowbase + mt * 16 + gid;
            int c0 = ccolbase + nt * 8 + tig * 2;
            *(float2*)(C + r0 * N + c0) =
                make_float2(acc[mt][nt][0], acc[mt][nt][1]);
            *(float2*)(C + (r0 + 8) * N + c0) =
                make_float2(acc[mt][nt][2], acc[mt][nt][3]);
        }
    }
}

// ---------------------------------------------------------------------------
// QK RMSNorm + RoPE + query scaling; also scatters V into [B,K,T,H] layout.
// ---------------------------------------------------------------------------
__global__ __launch_bounds__(128) void qk_rope_kernel(
    const int* __restrict__ segpos,
    const float* __restrict__ qns, const float* __restrict__ kns)
{
    const int row = blockIdx.x;       // b*T + t
    const int u = blockIdx.y;         // 0..31
    const int h = threadIdx.x;        // 0..127
    const int b = row >> 10;
    const int t = row & (T_ - 1);

    if (u >= NH + KH) {               // V: plain copy into [B,K,T,H]
        int kk = u - NH - KH;
        g_v[(((size_t)b * KH + kk) * T_ + t) * HD + h] =
            g_qkv[(size_t)row * QKVW + 3072 + kk * HD + h];
        return;
    }
    const bool isq = (u < NH);
    const int head = isq ? u : (u - NH);
    float val = g_qkv[(size_t)row * QKVW + (isq ? head * HD : 2048 + head * HD) + h];

    float ss = val * val;
    ss += __shfl_xor_sync(0xffffffffu, ss, 16);
    ss += __shfl_xor_sync(0xffffffffu, ss, 8);
    ss += __shfl_xor_sync(0xffffffffu, ss, 4);
    ss += __shfl_xor_sync(0xffffffffu, ss, 2);
    ss += __shfl_xor_sync(0xffffffffu, ss, 1);
    __shared__ float wsum[4];
    if ((h & 31) == 0) wsum[h >> 5] = ss;
    __syncthreads();
    float tot = wsum[0] + wsum[1] + wsum[2] + wsum[3];
    float r = rsqrtf(tot * (1.f / HD) + 1e-6f);
    float sc = isq ? qns[h] : kns[h];
    __shared__ float sv[HD];
    sv[h] = val * r * (1.f + sc);
    __syncthreads();

    // RoPE: timescale = 10000^(i/64) computed via exp2 (cheap MUFU path)
    int i = h & 63;
    float ts = exp2f((float)i * 0.20762050593046f);  // log2(10000)/64
    float ang = (float)segpos[row] / ts;
    float s, c;
    sincosf(ang, &s, &c);
    float out;
    if (h < 64) out = sv[h] * c - sv[h + 64] * s;
    else        out = sv[h] * c + sv[h - 64] * s;

    if (isq) {
        out *= 0.08838834764831845f;  // 128^-0.5
        g_q[(((size_t)b * NH + head) * T_ + t) * HD + h] = out;
    } else {
        g_k[(((size_t)b * KH + head) * T_ + t) * HD + h] = out;
    }
}

// ---------------------------------------------------------------------------
// Sliding-window GQA attention with tanh soft-cap (fp32, no online max).
// grid: (T/32, NH, B); block 128. Each 8-lane group handles 2 queries.
// float4 K/V loads: lines at word sub*4 + j*32 cover banks 0..31 exactly
// once (8 lines x 4 words, broadcast across 4 groups) -> conflict-free.
// ---------------------------------------------------------------------------
__global__ __launch_bounds__(128) void attn_kernel()
{
    const int b = blockIdx.z, n = blockIdx.y;
    const int q0 = blockIdx.x * 32;
    const int kh = n >> 1;                       // G = NH/KH = 2
    const int w = threadIdx.x >> 5, lane = threadIdx.x & 31;
    const int g = lane >> 3, sub = lane & 7;
    const int qA = q0 + (w * 4 + g) * 2;
    const int qB = qA + 1;

    const float* Kbase = g_k + (size_t)(b * KH + kh) * T_ * HD;
    const float* Vbase = g_v + (size_t)(b * KH + kh) * T_ * HD;
    const float* QbA   = g_q + (((size_t)(b * NH + n)) * T_ + qA) * HD;

    __shared__ float Ks[32 * HD];
    __shared__ float Vs[32 * HD];

    const int d0 = sub * 4;                      // this lane's dim base

    float4 qrA[4], qrB[4], oA[4], oB[4];
#pragma unroll
    for (int j = 0; j < 4; j++) {
        qrA[j] = *(const float4*)(QbA + d0 + j * 32);
        qrB[j] = *(const float4*)(QbA + HD + d0 + j * 32);
        oA[j] = make_float4(0.f, 0.f, 0.f, 0.f);
        oB[j] = make_float4(0.f, 0.f, 0.f, 0.f);
    }
    float dA = 0.f, dB = 0.f;

    int cstart = q0 - (WINDOW - 1);
    if (cstart < 0) cstart = 0;
    cstart &= ~31;

    for (int c = cstart; c <= q0 + 31; c += 32) {
        __syncthreads();
#pragma unroll
        for (int it = 0; it < 8; it++) {
            int idx = threadIdx.x + it * 128;     // float4 index 0..1023
            int r = idx >> 5, c4 = (idx & 31) << 2;
            *(float4*)(Ks + r * HD + c4) =
                *(const float4*)(Kbase + (size_t)(c + r) * HD + c4);
            *(float4*)(Vs + r * HD + c4) =
                *(const float4*)(Vbase + (size_t)(c + r) * HD + c4);
        }
        __syncthreads();
        for (int kk = 0; kk < 32; kk++) {
            const int tk = c + kk;
            float pa = 0.f, pb = 0.f;
            const float* kr = Ks + kk * HD + d0;
#pragma unroll
            for (int j = 0; j < 4; j++) {
                float4 kv = *(const float4*)(kr + j * 32);
                pa += qrA[j].x * kv.x + qrA[j].y * kv.y
                    + qrA[j].z * kv.z + qrA[j].w * kv.w;
                pb += qrB[j].x * kv.x + qrB[j].y * kv.y
                    + qrB[j].z * kv.z + qrB[j].w * kv.w;
            }
            pa += __shfl_xor_sync(0xffffffffu, pa, 1);
            pa += __shfl_xor_sync(0xffffffffu, pa, 2);
            pa += __shfl_xor_sync(0xffffffffu, pa, 4);
            pb += __shfl_xor_sync(0xffffffffu, pb, 1);
            pb += __shfl_xor_sync(0xffffffffu, pb, 2);
            pb += __shfl_xor_sync(0xffffffffu, pb, 4);
            float ca = 50.f * tanhf(pa * 0.02f);
            float cb = 50.f * tanhf(pb * 0.02f);
            float ea = (tk <= qA && tk > qA - WINDOW) ? __expf(ca) : 0.f;
            float eb = (tk <= qB && tk > qB - WINDOW) ? __expf(cb) : 0.f;
            dA += ea; dB += eb;
            const float* vr = Vs + kk * HD + d0;
#pragma unroll
            for (int j = 0; j < 4; j++) {
                float4 vv = *(const float4*)(vr + j * 32);
                oA[j].x += ea * vv.x; oA[j].y += ea * vv.y;
                oA[j].z += ea * vv.z; oA[j].w += ea * vv.w;
                oB[j].x += eb * vv.x; oB[j].y += eb * vv.y;
                oB[j].z += eb * vv.z; oB[j].w += eb * vv.w;
            }
        }
    }
    float iA = 1.f / dA, iB = 1.f / dB;
    float* encA = g_enc + ((size_t)(b * T_ + qA)) * D_ + n * HD;
#pragma unroll
    for (int j = 0; j < 4; j++) {
        *(float4*)(encA + d0 + j * 32) =
            make_float4(oA[j].x * iA, oA[j].y * iA, oA[j].z * iA, oA[j].w * iA);
        *(float4*)(encA + D_ + d0 + j * 32) =
            make_float4(oB[j].x * iB, oB[j].y * iB, oB[j].z * iB, oB[j].w * iB);
    }
}

// ---------------------------------------------------------------------------
// Fused: attn_out = rmsnorm(attn_raw)*(1+post_s) + x ; h2 = rmsnorm(attn_out)*(1+pre_ffw)
// ---------------------------------------------------------------------------
__global__ __launch_bounds__(256) void postattn_kernel(
    const float* __restrict__ x,
    const float* __restrict__ ps, const float* __restrict__ fs)
{
    const size_t base = (size_t)blockIdx.x * D_;
    float loc[8]; float ss = 0.f;
#pragma unroll
    for (int j = 0; j < 8; j++) {
        float v = g_attnraw[base + threadIdx.x + j * 256];
        loc[j] = v; ss += v * v;
    }
    float tot = blockSum256(ss);
    float r1 = rsqrtf(tot * (1.f / D_) + 1e-6f);
    float ao[8]; float ss2 = 0.f;
#pragma unroll
    for (int j = 0; j < 8; j++) {
        int idx = threadIdx.x + j * 256;
        float v = loc[j] * r1 * (1.f + ps[idx]) + x[base + idx];
        ao[j] = v; ss2 += v * v;
        g_attnout[base + idx] = v;
    }
    float tot2 = blockSum256(ss2);
    float r2 = rsqrtf(tot2 * (1.f / D_) + 1e-6f);
#pragma unroll
    for (int j = 0; j < 8; j++) {
        int idx = threadIdx.x + j * 256;
        g_h2[base + idx] = ao[j] * r2 * (1.f + fs[idx]);
    }
}

// ---------------------------------------------------------------------------
// act = gelu_tanh(gate) * up
// ---------------------------------------------------------------------------
__global__ __launch_bounds__(256) void gelu_mul_kernel()
{
    size_t i4 = (size_t)blockIdx.x * blockDim.x + threadIdx.x;
    const size_t total4 = (size_t)MT * HID_ / 4;
    if (i4 >= total4) return;
    float4 gv = ((const float4*)g_gate)[i4];
    float4 uv = ((const float4*)g_up)[i4];
    float r[4]; float gs[4] = {gv.x, gv.y, gv.z, gv.w};
    float us[4] = {uv.x, uv.y, uv.z, uv.w};
#pragma unroll
    for (int j = 0; j < 4; j++) {
        float x = gs[j];
        float t = tanhf(0.7978845608028654f * (x + 0.044715f * x * x * x));
        r[j] = 0.5f * x * (1.f + t) * us[j];
    }
    ((float4*)g_act)[i4] = make_float4(r[0], r[1], r[2], r[3]);
}

// ---------------------------------------------------------------------------
// Final: out = rmsnorm(out_raw)*(1+post_ffw) + attn_out
// ---------------------------------------------------------------------------
__global__ __launch_bounds__(256) void final_kernel(
    const float* __restrict__ ps, float* __restrict__ out)
{
    const size_t base = (size_t)blockIdx.x * D_;
    float loc[8]; float ss = 0.f;
#pragma unroll
    for (int j = 0; j < 8; j++) {
        float v = g_outraw[base + threadIdx.x + j * 256];
        loc[j] = v; ss += v * v;
    }
    float tot = blockSum256(ss);
    float r = rsqrtf(tot * (1.f / D_) + 1e-6f);
#pragma unroll
    for (int j = 0; j < 8; j++) {
        int idx = threadIdx.x + j * 256;
        out[base + idx] = loc[j] * r * (1.f + ps[idx]) + g_attnout[base + idx];
    }
}

// ---------------------------------------------------------------------------
// Launch
// ---------------------------------------------------------------------------
extern "C" void kernel_launch(void* const* d_in, const int* in_sizes, int n_in,
                              void* d_out, int out_size)
{
    const float* x        = (const float*)d_in[0];
    const int*   segpos   = (const int*)d_in[1];
    /* d_in[2] = attn_mask (causal tril) — mask computed analytically */
    const float* qkern    = (const float*)d_in[3];
    const float* kvkern   = (const float*)d_in[4];
    const float* okern    = (const float*)d_in[5];
    const float* gate_w   = (const float*)d_in[6];
    const float* up_w     = (const float*)d_in[7];
    const float* down_w   = (const float*)d_in[8];
    const float* pre_attn = (const float*)d_in[9];
    const float* post_attn= (const float*)d_in[10];
    const float* pre_ffw  = (const float*)d_in[11];
    const float* post_ffw = (const float*)d_in[12];
    const float* qns      = (const float*)d_in[13];
    const float* kns      = (const float*)d_in[14];
    float* out = (float*)d_out;

    float *p_h, *p_wpack, *p_qkv, *p_enc, *p_araw, *p_h2, *p_gate, *p_up,
          *p_act, *p_oraw;
    cudaGetSymbolAddress((void**)&p_h, g_h);
    cudaGetSymbolAddress((void**)&p_wpack, g_wpack);
    cudaGetSymbolAddress((void**)&p_qkv, g_qkv);
    cudaGetSymbolAddress((void**)&p_enc, g_enc);
    cudaGetSymbolAddress((void**)&p_araw, g_attnraw);
    cudaGetSymbolAddress((void**)&p_h2, g_h2);
    cudaGetSymbolAddress((void**)&p_gate, g_gate);
    cudaGetSymbolAddress((void**)&p_up, g_up);
    cudaGetSymbolAddress((void**)&p_act, g_act);
    cudaGetSymbolAddress((void**)&p_oraw, g_outraw);

    // Allow 56.8 KB dynamic smem for the 3-stage GEMM (idempotent host call)
    cudaFuncSetAttribute(gemm_tf32,
                         cudaFuncAttributeMaxDynamicSharedMemorySize, GEMM_SMEM);

    // 1. pre-attn rmsnorm
    rmsnorm_kernel<<<MT, 256>>>(x, pre_attn, p_h);

    // 2. pack qkv weights into [D, 4096]
    {
        size_t total = (size_t)D_ * QKVW;
        pack_kernel<<<(unsigned)((total + 255) / 256), 256>>>(qkern, kvkern);
    }

    // 3. QKV GEMM: [2048,2048] x [2048,4096]
    gemm_tf32<<<dim3(QKVW / GBN, MT / GBM), 256, GEMM_SMEM>>>(
        p_h, p_wpack, p_qkv, MT, QKVW, D_);

    // 4. QK norm + RoPE + scatter
    qk_rope_kernel<<<dim3(MT, NH + 2 * KH), 128>>>(segpos, qns, kns);

    // 5. attention
    attn_kernel<<<dim3(T_ / 32, NH, B_), 128>>>();

    // 6. O projection: [2048,2048] x [2048,2048]
    gemm_tf32<<<dim3(D_ / GBN, MT / GBM), 256, GEMM_SMEM>>>(
        p_enc, okern, p_araw, MT, D_, D_);

    // 7. post-attn norm + residual + pre-ffw norm
    postattn_kernel<<<MT, 256>>>(x, post_attn, pre_ffw);

    // 8. MLP up/gate GEMMs: [2048,2048] x [2048,8192]
    gemm_tf32<<<dim3(HID_ / GBN, MT / GBM), 256, GEMM_SMEM>>>(
        p_h2, gate_w, p_gate, MT, HID_, D_);
    gemm_tf32<<<dim3(HID_ / GBN, MT / GBM), 256, GEMM_SMEM>>>(
        p_h2, up_w, p_up, MT, HID_, D_);

    // 9. gated GELU
    {
        size_t total4 = (size_t)MT * HID_ / 4;
        gelu_mul_kernel<<<(unsigned)((total4 + 255) / 256), 256>>>();
    }

    // 10. down GEMM: [2048,8192] x [8192,2048]
    gemm_tf32<<<dim3(D_ / GBN, MT / GBM), 256, GEMM_SMEM>>>(
        p_act, down_w, p_oraw, MT, D_, HID_);

    // 11. final norm + residual
    final_kernel<<<MT, 256>>>(post_ffw, out);
}

// round 16
// speedup vs baseline: 1.1125x; 1.1042x over previous
#include <cuda_runtime.h>
#include <cuda_bf16.h>
#include <math.h>
#include <stdint.h>

// ---------------------------------------------------------------------------
// Problem dims (fixed by the dataset)
// ---------------------------------------------------------------------------
#define B_  2
#define T_  1024
#define D_  2048
#define NH  16
#define KH  8
#define HD  128
#define HID_ 8192
#define MT  (B_ * T_)            // 2048 token rows
#define QKVW 4096                // NH*HD + KH*HD + KH*HD
#define WINDOW 512

// ---------------------------------------------------------------------------
// Scratch (static device arrays — allocation-free per harness rules)
// ---------------------------------------------------------------------------
__device__ float g_h      [(size_t)MT * D_];
__device__ float g_wpack  [(size_t)D_ * QKVW];
__device__ float g_qkv    [(size_t)MT * QKVW];
__device__ float g_q      [(size_t)B_ * NH * T_ * HD];
__device__ float g_k      [(size_t)B_ * KH * T_ * HD];
__device__ float g_v      [(size_t)B_ * KH * T_ * HD];
__device__ float g_enc    [(size_t)MT * D_];
__device__ float g_attnraw[(size_t)MT * D_];
__device__ float g_attnout[(size_t)MT * D_];
__device__ float g_h2     [(size_t)MT * D_];
__device__ float g_gate   [(size_t)MT * HID_];
__device__ float g_up     [(size_t)MT * HID_];
__device__ float g_act    [(size_t)MT * HID_];
__device__ float g_outraw [(size_t)MT * D_];
// tf32-rounded weight copies (GEMM B operands; avoids in-loop cvt)
__device__ float g_wok    [(size_t)D_ * D_];
__device__ float g_wgate  [(size_t)D_ * HID_];
__device__ float g_wup    [(size_t)D_ * HID_];
__device__ float g_wdown  [(size_t)HID_ * D_];

// ---------------------------------------------------------------------------
// tf32 rounding helpers (rna; idempotent)
// ---------------------------------------------------------------------------
__device__ __forceinline__ float tf32r(float x) {
    uint32_t u;
    asm("cvt.rna.tf32.f32 %0, %1;" : "=r"(u) : "f"(x));
    return __uint_as_float(u);
}

// ---------------------------------------------------------------------------
// Block reduction (256 threads)
// ---------------------------------------------------------------------------
__device__ __forceinline__ float blockSum256(float v) {
    __shared__ float sm[8];
    v += __shfl_xor_sync(0xffffffffu, v, 16);
    v += __shfl_xor_sync(0xffffffffu, v, 8);
    v += __shfl_xor_sync(0xffffffffu, v, 4);
    v += __shfl_xor_sync(0xffffffffu, v, 2);
    v += __shfl_xor_sync(0xffffffffu, v, 1);
    if ((threadIdx.x & 31) == 0) sm[threadIdx.x >> 5] = v;
    __syncthreads();
    float t = sm[0] + sm[1] + sm[2] + sm[3] + sm[4] + sm[5] + sm[6] + sm[7];
    __syncthreads();
    return t;
}

// ---------------------------------------------------------------------------
// Pre-attn RMSNorm (output tf32-rounded: feeds QKV GEMM only)
// ---------------------------------------------------------------------------
__global__ __launch_bounds__(256) void rmsnorm_kernel(
    const float* __restrict__ in, const float* __restrict__ scale,
    float* __restrict__ out)
{
    const size_t base = (size_t)blockIdx.x * D_;
    float loc[8]; float ss = 0.f;
#pragma unroll
    for (int j = 0; j < 8; j++) {
        float v = in[base + threadIdx.x + j * 256];
        loc[j] = v; ss += v * v;
    }
    float tot = blockSum256(ss);
    float r = rsqrtf(tot * (1.f / D_) + 1e-6f);
#pragma unroll
    for (int j = 0; j < 8; j++) {
        int idx = threadIdx.x + j * 256;
        out[base + idx] = tf32r(loc[j] * r * (1.f + scale[idx]));
    }
}

// ---------------------------------------------------------------------------
// Pack q_kernel [N,D,H] and kv_kernel [2,K,D,H] into Wpack [D, 4096], tf32.
// ---------------------------------------------------------------------------
__global__ __launch_bounds__(256) void pack_kernel(
    const float* __restrict__ qk, const float* __restrict__ kvk)
{
    size_t i = (size_t)blockIdx.x * blockDim.x + threadIdx.x;
    const size_t total = (size_t)D_ * QKVW;
    if (i >= total) return;
    int d = (int)(i >> 12);
    int col = (int)(i & (QKVW - 1));
    float v;
    if (col < 2048) {
        int n = col >> 7, hh = col & 127;
        v = qk[((size_t)n * D_ + d) * HD + hh];
    } else if (col < 3072) {
        int cc = col - 2048; int kk2 = cc >> 7, hh = cc & 127;
        v = kvk[((size_t)kk2 * D_ + d) * HD + hh];
    } else {
        int cc = col - 3072; int kk2 = cc >> 7, hh = cc & 127;
        v = kvk[(size_t)KH * D_ * HD + ((size_t)kk2 * D_ + d) * HD + hh];
    }
    g_wpack[i] = tf32r(v);
}

// ---------------------------------------------------------------------------
// Bulk tf32 rounding copy (for weight matrices), float4 vectorized.
// ---------------------------------------------------------------------------
__global__ __launch_bounds__(256) void tf32_copy_kernel(
    const float* __restrict__ in, float* __restrict__ out, size_t n4)
{
    size_t i = (size_t)blockIdx.x * blockDim.x + threadIdx.x;
    if (i >= n4) return;
    float4 v = ((const float4*)in)[i];
    ((float4*)out)[i] = make_float4(tf32r(v.x), tf32r(v.y), tf32r(v.z), tf32r(v.w));
}

// ---------------------------------------------------------------------------
// TF32 tensor-core GEMM, 3-stage cp.async pipeline, cvt-free inner loop.
// All operands pre-rounded to tf32 in gmem; fragments loaded as raw uint32.
// C[M,N] = A[M,K] * B[K,N], row-major. M%128==0, N%128==0, K%16==0, K/16>=3.
// 256 threads = 8 warps in 2x4; warp computes 64x32 via 4x4 m16n8k8 tiles.
// A staged m-major (stride 20w), B k-row-major (stride 136w); both
// bank-conflict-free for fragment LDS (A: 20g+t; B: 8t+g patterns).
// __launch_bounds__(256,2): 2 CTAs/SM for latency hiding.
// ---------------------------------------------------------------------------
#define GBM 128
#define GBN 128
#define GBK 16
#define A_STRIDE 20                        // words per A row (16 data + 4 pad)
#define B_STRIDE 136                       // words per B row (128 data + 8 pad)
#define A_BYTES (GBM * A_STRIDE * 4)       // 10240
#define B_BYTES (GBK * B_STRIDE * 4)       // 8704
#define STAGE_BYTES (A_BYTES + B_BYTES)    // 18944
#define GEMM_SMEM (3 * STAGE_BYTES)        // 56832

__device__ __forceinline__ void cp16(void* sdst, const void* gsrc) {
    unsigned s = (unsigned)__cvta_generic_to_shared(sdst);
    asm volatile("cp.async.cg.shared.global [%0], [%1], 16;"
                 :: "r"(s), "l"(gsrc) : "memory");
}

__device__ __forceinline__ void mma_tf32(
    float c[4], const uint32_t a[4], const uint32_t b[2])
{
    asm volatile(
        "mma.sync.aligned.m16n8k8.row.col.f32.tf32.tf32.f32 "
        "{%0,%1,%2,%3}, {%4,%5,%6,%7}, {%8,%9}, {%0,%1,%2,%3};"
        : "+f"(c[0]), "+f"(c[1]), "+f"(c[2]), "+f"(c[3])
        : "r"(a[0]), "r"(a[1]), "r"(a[2]), "r"(a[3]),
          "r"(b[0]), "r"(b[1]));
}

__global__ __launch_bounds__(256, 2) void gemm_tf32(
    const float* __restrict__ A, const float* __restrict__ B,
    float* __restrict__ C, int M, int N, int K)
{
    extern __shared__ char smem[];

    const int tid = threadIdx.x;
    const int lane = tid & 31;
    const int wid = tid >> 5;
    const int warpRow = wid >> 2;           // 0..1 -> 64-row slab
    const int warpCol = wid & 3;            // 0..3 -> 32-col slab
    const int gid = lane >> 2;              // groupID 0..7
    const int tig = lane & 3;               // thread-in-group 0..3

    const float* Ablk = A + (size_t)blockIdx.y * GBM * K;
    const float* Bblk = B + (size_t)blockIdx.x * GBN;

    // staging thread mapping: per thread 2x16B for A, 2x16B for B
    const int arow = tid >> 1;              // 0..127
    const int acg  = (tid & 1) << 3;        // k-subgroup 0 or 8
    const int brow = tid >> 4;              // 0..15
    const int bcol = (tid & 15) << 3;       // 0..120

    float acc[4][4][4];
#pragma unroll
    for (int mt = 0; mt < 4; mt++)
#pragma unroll
        for (int nt = 0; nt < 4; nt++)
#pragma unroll
            for (int r = 0; r < 4; r++) acc[mt][nt][r] = 0.f;

#define A_ST(s) ((float*)(smem + (s) * STAGE_BYTES))
#define B_ST(s) ((float*)(smem + (s) * STAGE_BYTES + A_BYTES))

#define ISSUE_TILE(s, k0)                                                      \
    {                                                                          \
        float* As_ = A_ST(s) + arow * A_STRIDE + acg;                          \
        const float* ag = Ablk + (size_t)arow * K + (k0) + acg;                \
        cp16(As_, ag);                                                         \
        cp16(As_ + 4, ag + 4);                                                 \
        float* Bs_ = B_ST(s) + brow * B_STRIDE + bcol;                         \
        const float* bg = Bblk + (size_t)((k0) + brow) * N + bcol;             \
        cp16(Bs_, bg);                                                         \
        cp16(Bs_ + 4, bg + 4);                                                 \
        asm volatile("cp.async.commit_group;" ::: "memory");                   \
    }

    const int T = K / GBK;
    ISSUE_TILE(0, 0);
    ISSUE_TILE(1, GBK);

    int cur = 0;
    for (int k = 0; k < T; k++) {
        if (k + 1 < T) {
            asm volatile("cp.async.wait_group 1;" ::: "memory");
        } else {
            asm volatile("cp.async.wait_group 0;" ::: "memory");
        }
        __syncthreads();
        if (k + 2 < T) {
            int s = (k + 2) % 3;            // consumers passed barrier
            ISSUE_TILE(s, (k + 2) * GBK);
        }

        const uint32_t* As = (const uint32_t*)A_ST(cur);
        const uint32_t* Bs = (const uint32_t*)B_ST(cur);
#pragma unroll
        for (int ks = 0; ks < 2; ks++) {
            const int k8 = ks * 8;
            uint32_t afr[4][4], bfr[4][2];
#pragma unroll
            for (int mt = 0; mt < 4; mt++) {
                int m0 = warpRow * 64 + mt * 16 + gid;
                afr[mt][0] = As[(size_t)m0 * A_STRIDE + k8 + tig];
                afr[mt][1] = As[(size_t)(m0 + 8) * A_STRIDE + k8 + tig];
                afr[mt][2] = As[(size_t)m0 * A_STRIDE + k8 + tig + 4];
                afr[mt][3] = As[(size_t)(m0 + 8) * A_STRIDE + k8 + tig + 4];
            }
#pragma unroll
            for (int nt = 0; nt < 4; nt++) {
                int n0 = warpCol * 32 + nt * 8 + gid;
                bfr[nt][0] = Bs[(size_t)(k8 + tig) * B_STRIDE + n0];
                bfr[nt][1] = Bs[(size_t)(k8 + tig + 4) * B_STRIDE + n0];
            }
#pragma unroll
            for (int mt = 0; mt < 4; mt++)
#pragma unroll
                for (int nt = 0; nt < 4; nt++)
                    mma_tf32(acc[mt][nt], afr[mt], bfr[nt]);
        }
        cur = (cur + 1) % 3;
    }
#undef ISSUE_TILE
#undef A_ST
#undef B_ST

    // Epilogue: c0 (gid, 2*tig), c1 (gid, 2*tig+1), c2 (+8 row), c3.
    const size_t crowbase = (size_t)blockIdx.y * GBM + warpRow * 64;
    const int ccolbase = blockIdx.x * GBN + warpCol * 32;
#pragma unroll
    for (int mt = 0; mt < 4; mt++) {
#pragma unroll
        for (int nt = 0; nt < 4; nt++) {
            size_t r0 = crowbase + mt * 16 + gid;
            int c0 = ccolbase + nt * 8 + tig * 2;
            *(float2*)(C + r0 * N + c0) =
                make_float2(acc[mt][nt][0], acc[mt][nt][1]);
            *(float2*)(C + (r0 + 8) * N + c0) =
                make_float2(acc[mt][nt][2], acc[mt][nt][3]);
        }
    }
}

// ---------------------------------------------------------------------------
// QK RMSNorm + RoPE + query scaling; also scatters V into [B,K,T,H] layout.
// ---------------------------------------------------------------------------
__global__ __launch_bounds__(128) void qk_rope_kernel(
    const int* __restrict__ segpos,
    const float* __restrict__ qns, const float* __restrict__ kns)
{
    const int row = blockIdx.x;       // b*T + t
    const int u = blockIdx.y;         // 0..31
    const int h = threadIdx.x;        // 0..127
    const int b = row >> 10;
    const int t = row & (T_ - 1);

    if (u >= NH + KH) {               // V: plain copy into [B,K,T,H]
        int kk = u - NH - KH;
        g_v[(((size_t)b * KH + kk) * T_ + t) * HD + h] =
            g_qkv[(size_t)row * QKVW + 3072 + kk * HD + h];
        return;
    }
    const bool isq = (u < NH);
    const int head = isq ? u : (u - NH);
    float val = g_qkv[(size_t)row * QKVW + (isq ? head * HD : 2048 + head * HD) + h];

    float ss = val * val;
    ss += __shfl_xor_sync(0xffffffffu, ss, 16);
    ss += __shfl_xor_sync(0xffffffffu, ss, 8);
    ss += __shfl_xor_sync(0xffffffffu, ss, 4);
    ss += __shfl_xor_sync(0xffffffffu, ss, 2);
    ss += __shfl_xor_sync(0xffffffffu, ss, 1);
    __shared__ float wsum[4];
    if ((h & 31) == 0) wsum[h >> 5] = ss;
    __syncthreads();
    float tot = wsum[0] + wsum[1] + wsum[2] + wsum[3];
    float r = rsqrtf(tot * (1.f / HD) + 1e-6f);
    float sc = isq ? qns[h] : kns[h];
    __shared__ float sv[HD];
    sv[h] = val * r * (1.f + sc);
    __syncthreads();

    // RoPE: timescale = 10000^(i/64) via exp2 (MUFU path)
    int i = h & 63;
    float ts = exp2f((float)i * 0.20762050593046f);  // log2(10000)/64
    float ang = (float)segpos[row] / ts;
    float s, c;
    sincosf(ang, &s, &c);
    float out;
    if (h < 64) out = sv[h] * c - sv[h + 64] * s;
    else        out = sv[h] * c + sv[h - 64] * s;

    if (isq) {
        out *= 0.08838834764831845f;  // 128^-0.5
        g_q[(((size_t)b * NH + head) * T_ + t) * HD + h] = out;
    } else {
        g_k[(((size_t)b * KH + head) * T_ + t) * HD + h] = out;
    }
}

// ---------------------------------------------------------------------------
// Sliding-window GQA attention with tanh soft-cap (fp32, no online max).
// grid: (T/32, NH, B); block 128. Each 8-lane group handles 2 queries.
// enc output tf32-rounded (feeds O-proj GEMM only).
// ---------------------------------------------------------------------------
__global__ __launch_bounds__(128) void attn_kernel()
{
    const int b = blockIdx.z, n = blockIdx.y;
    const int q0 = blockIdx.x * 32;
    const int kh = n >> 1;                       // G = NH/KH = 2
    const int w = threadIdx.x >> 5, lane = threadIdx.x & 31;
    const int g = lane >> 3, sub = lane & 7;
    const int qA = q0 + (w * 4 + g) * 2;
    const int qB = qA + 1;

    const float* Kbase = g_k + (size_t)(b * KH + kh) * T_ * HD;
    const float* Vbase = g_v + (size_t)(b * KH + kh) * T_ * HD;
    const float* QbA   = g_q + (((size_t)(b * NH + n)) * T_ + qA) * HD;

    __shared__ float Ks[32 * HD];
    __shared__ float Vs[32 * HD];

    const int d0 = sub * 4;                      // this lane's dim base

    float4 qrA[4], qrB[4], oA[4], oB[4];
#pragma unroll
    for (int j = 0; j < 4; j++) {
        qrA[j] = *(const float4*)(QbA + d0 + j * 32);
        qrB[j] = *(const float4*)(QbA + HD + d0 + j * 32);
        oA[j] = make_float4(0.f, 0.f, 0.f, 0.f);
        oB[j] = make_float4(0.f, 0.f, 0.f, 0.f);
    }
    float dA = 0.f, dB = 0.f;

    int cstart = q0 - (WINDOW - 1);
    if (cstart < 0) cstart = 0;
    cstart &= ~31;

    for (int c = cstart; c <= q0 + 31; c += 32) {
        __syncthreads();
#pragma unroll
        for (int it = 0; it < 8; it++) {
            int idx = threadIdx.x + it * 128;     // float4 index 0..1023
            int r = idx >> 5, c4 = (idx & 31) << 2;
            *(float4*)(Ks + r * HD + c4) =
                *(const float4*)(Kbase + (size_t)(c + r) * HD + c4);
            *(float4*)(Vs + r * HD + c4) =
                *(const float4*)(Vbase + (size_t)(c + r) * HD + c4);
        }
        __syncthreads();
        for (int kk = 0; kk < 32; kk++) {
            const int tk = c + kk;
            float pa = 0.f, pb = 0.f;
            const float* kr = Ks + kk * HD + d0;
#pragma unroll
            for (int j = 0; j < 4; j++) {
                float4 kv = *(const float4*)(kr + j * 32);
                pa += qrA[j].x * kv.x + qrA[j].y * kv.y
                    + qrA[j].z * kv.z + qrA[j].w * kv.w;
                pb += qrB[j].x * kv.x + qrB[j].y * kv.y
                    + qrB[j].z * kv.z + qrB[j].w * kv.w;
            }
            pa += __shfl_xor_sync(0xffffffffu, pa, 1);
            pa += __shfl_xor_sync(0xffffffffu, pa, 2);
            pa += __shfl_xor_sync(0xffffffffu, pa, 4);
            pb += __shfl_xor_sync(0xffffffffu, pb, 1);
            pb += __shfl_xor_sync(0xffffffffu, pb, 2);
            pb += __shfl_xor_sync(0xffffffffu, pb, 4);
            float ca = 50.f * tanhf(pa * 0.02f);
            float cb = 50.f * tanhf(pb * 0.02f);
            float ea = (tk <= qA && tk > qA - WINDOW) ? __expf(ca) : 0.f;
            float eb = (tk <= qB && tk > qB - WINDOW) ? __expf(cb) : 0.f;
            dA += ea; dB += eb;
            const float* vr = Vs + kk * HD + d0;
#pragma unroll
            for (int j = 0; j < 4; j++) {
                float4 vv = *(const float4*)(vr + j * 32);
                oA[j].x += ea * vv.x; oA[j].y += ea * vv.y;
                oA[j].z += ea * vv.z; oA[j].w += ea * vv.w;
                oB[j].x += eb * vv.x; oB[j].y += eb * vv.y;
                oB[j].z += eb * vv.z; oB[j].w += eb * vv.w;
            }
        }
    }
    float iA = 1.f / dA, iB = 1.f / dB;
    float* encA = g_enc + ((size_t)(b * T_ + qA)) * D_ + n * HD;
#pragma unroll
    for (int j = 0; j < 4; j++) {
        *(float4*)(encA + d0 + j * 32) =
            make_float4(tf32r(oA[j].x * iA), tf32r(oA[j].y * iA),
                        tf32r(oA[j].z * iA), tf32r(oA[j].w * iA));
        *(float4*)(encA + D_ + d0 + j * 32) =
            make_float4(tf32r(oB[j].x * iB), tf32r(oB[j].y * iB),
                        tf32r(oB[j].z * iB), tf32r(oB[j].w * iB));
    }
}

// ---------------------------------------------------------------------------
// Fused: attn_out = rmsnorm(attn_raw)*(1+post_s) + x ; h2 = rmsnorm(attn_out)*(1+pre_ffw)
// attn_out kept full fp32 (residual stream); h2 tf32-rounded (GEMM input).
// ---------------------------------------------------------------------------
__global__ __launch_bounds__(256) void postattn_kernel(
    const float* __restrict__ x,
    const float* __restrict__ ps, const float* __restrict__ fs)
{
    const size_t base = (size_t)blockIdx.x * D_;
    float loc[8]; float ss = 0.f;
#pragma unroll
    for (int j = 0; j < 8; j++) {
        float v = g_attnraw[base + threadIdx.x + j * 256];
        loc[j] = v; ss += v * v;
    }
    float tot = blockSum256(ss);
    float r1 = rsqrtf(tot * (1.f / D_) + 1e-6f);
    float ao[8]; float ss2 = 0.f;
#pragma unroll
    for (int j = 0; j < 8; j++) {
        int idx = threadIdx.x + j * 256;
        float v = loc[j] * r1 * (1.f + ps[idx]) + x[base + idx];
        ao[j] = v; ss2 += v * v;
        g_attnout[base + idx] = v;
    }
    float tot2 = blockSum256(ss2);
    float r2 = rsqrtf(tot2 * (1.f / D_) + 1e-6f);
#pragma unroll
    for (int j = 0; j < 8; j++) {
        int idx = threadIdx.x + j * 256;
        g_h2[base + idx] = tf32r(ao[j] * r2 * (1.f + fs[idx]));
    }
}

// ---------------------------------------------------------------------------
// act = gelu_tanh(gate) * up  (tf32-rounded: feeds down GEMM only)
// ---------------------------------------------------------------------------
__global__ __launch_bounds__(256) void gelu_mul_kernel()
{
    size_t i4 = (size_t)blockIdx.x * blockDim.x + threadIdx.x;
    const size_t total4 = (size_t)MT * HID_ / 4;
    if (i4 >= total4) return;
    float4 gv = ((const float4*)g_gate)[i4];
    float4 uv = ((const float4*)g_up)[i4];
    float r[4]; float gs[4] = {gv.x, gv.y, gv.z, gv.w};
    float us[4] = {uv.x, uv.y, uv.z, uv.w};
#pragma unroll
    for (int j = 0; j < 4; j++) {
        float x = gs[j];
        float t = tanhf(0.7978845608028654f * (x + 0.044715f * x * x * x));
        r[j] = tf32r(0.5f * x * (1.f + t) * us[j]);
    }
    ((float4*)g_act)[i4] = make_float4(r[0], r[1], r[2], r[3]);
}

// ---------------------------------------------------------------------------
// Final: out = rmsnorm(out_raw)*(1+post_ffw) + attn_out
// ---------------------------------------------------------------------------
__global__ __launch_bounds__(256) void final_kernel(
    const float* __restrict__ ps, float* __restrict__ out)
{
    const size_t base = (size_t)blockIdx.x * D_;
    float loc[8]; float ss = 0.f;
#pragma unroll
    for (int j = 0; j < 8; j++) {
        float v = g_outraw[base + threadIdx.x + j * 256];
        loc[j] = v; ss += v * v;
    }
    float tot = blockSum256(ss);
    float r = rsqrtf(tot * (1.f / D_) + 1e-6f);
#pragma unroll
    for (int j = 0; j < 8; j++) {
        int idx = threadIdx.x + j * 256;
        out[base + idx] = loc[j] * r * (1.f + ps[idx]) + g_attnout[base + idx];
    }
}

// ---------------------------------------------------------------------------
// Launch
// ---------------------------------------------------------------------------
extern "C" void kernel_launch(void* const* d_in, const int* in_sizes, int n_in,
                              void* d_out, int out_size)
{
    const float* x        = (const float*)d_in[0];
    const int*   segpos   = (const int*)d_in[1];
    /* d_in[2] = attn_mask (causal tril) — mask computed analytically */
    const float* qkern    = (const float*)d_in[3];
    const float* kvkern   = (const float*)d_in[4];
    const float* okern    = (const float*)d_in[5];
    const float* gate_w   = (const float*)d_in[6];
    const float* up_w     = (const float*)d_in[7];
    const float* down_w   = (const float*)d_in[8];
    const float* pre_attn = (const float*)d_in[9];
    const float* post_attn= (const float*)d_in[10];
    const float* pre_ffw  = (const float*)d_in[11];
    const float* post_ffw = (const float*)d_in[12];
    const float* qns      = (const float*)d_in[13];
    const float* kns      = (const float*)d_in[14];
    float* out = (float*)d_out;

    float *p_h, *p_wpack, *p_qkv, *p_enc, *p_araw, *p_h2, *p_gate, *p_up,
          *p_act, *p_oraw, *p_wok, *p_wgate, *p_wup, *p_wdown;
    cudaGetSymbolAddress((void**)&p_h, g_h);
    cudaGetSymbolAddress((void**)&p_wpack, g_wpack);
    cudaGetSymbolAddress((void**)&p_qkv, g_qkv);
    cudaGetSymbolAddress((void**)&p_enc, g_enc);
    cudaGetSymbolAddress((void**)&p_araw, g_attnraw);
    cudaGetSymbolAddress((void**)&p_h2, g_h2);
    cudaGetSymbolAddress((void**)&p_gate, g_gate);
    cudaGetSymbolAddress((void**)&p_up, g_up);
    cudaGetSymbolAddress((void**)&p_act, g_act);
    cudaGetSymbolAddress((void**)&p_oraw, g_outraw);
    cudaGetSymbolAddress((void**)&p_wok, g_wok);
    cudaGetSymbolAddress((void**)&p_wgate, g_wgate);
    cudaGetSymbolAddress((void**)&p_wup, g_wup);
    cudaGetSymbolAddress((void**)&p_wdown, g_wdown);

    cudaFuncSetAttribute(gemm_tf32,
                         cudaFuncAttributeMaxDynamicSharedMemorySize, GEMM_SMEM);

    // 1. pre-attn rmsnorm (tf32-rounded output)
    rmsnorm_kernel<<<MT, 256>>>(x, pre_attn, p_h);

    // 2. pack qkv weights into [D, 4096] (tf32) + round other weights
    {
        size_t total = (size_t)D_ * QKVW;
        pack_kernel<<<(unsigned)((total + 255) / 256), 256>>>(qkern, kvkern);
        size_t n4o = (size_t)D_ * D_ / 4;
        tf32_copy_kernel<<<(unsigned)((n4o + 255) / 256), 256>>>(okern, p_wok, n4o);
        size_t n4g = (size_t)D_ * HID_ / 4;
        tf32_copy_kernel<<<(unsigned)((n4g + 255) / 256), 256>>>(gate_w, p_wgate, n4g);
        tf32_copy_kernel<<<(unsigned)((n4g + 255) / 256), 256>>>(up_w, p_wup, n4g);
        size_t n4d = (size_t)HID_ * D_ / 4;
        tf32_copy_kernel<<<(unsigned)((n4d + 255) / 256), 256>>>(down_w, p_wdown, n4d);
    }

    // 3. QKV GEMM: [2048,2048] x [2048,4096]
    gemm_tf32<<<dim3(QKVW / GBN, MT / GBM), 256, GEMM_SMEM>>>(
        p_h, p_wpack, p_qkv, MT, QKVW, D_);

    // 4. QK norm + RoPE + scatter
    qk_rope_kernel<<<dim3(MT, NH + 2 * KH), 128>>>(segpos, qns, kns);

    // 5. attention (enc tf32-rounded)
    attn_kernel<<<dim3(T_ / 32, NH, B_), 128>>>();

    // 6. O projection: [2048,2048] x [2048,2048]
    gemm_tf32<<<dim3(D_ / GBN, MT / GBM), 256, GEMM_SMEM>>>(
        p_enc, p_wok, p_araw, MT, D_, D_);

    // 7. post-attn norm + residual + pre-ffw norm
    postattn_kernel<<<MT, 256>>>(x, post_attn, pre_ffw);

    // 8. MLP up/gate GEMMs: [2048,2048] x [2048,8192]
    gemm_tf32<<<dim3(HID_ / GBN, MT / GBM), 256, GEMM_SMEM>>>(
        p_h2, p_wgate, p_gate, MT, HID_, D_);
    gemm_tf32<<<dim3(HID_ / GBN, MT / GBM), 256, GEMM_SMEM>>>(
        p_h2, p_wup, p_up, MT, HID_, D_);

    // 9. gated GELU (tf32-rounded)
    {
        size_t total4 = (size_t)MT * HID_ / 4;
        gelu_mul_kernel<<<(unsigned)((total4 + 255) / 256), 256>>>();
    }

    // 10. down GEMM: [2048,8192] x [8192,2048]
    gemm_tf32<<<dim3(D_ / GBN, MT / GBM), 256, GEMM_SMEM>>>(
        p_act, p_wdown, p_oraw, MT, D_, HID_);

    // 11. final norm + residual
    final_kernel<<<MT, 256>>>(post_ffw, out);
}